// round 11
// baseline (speedup 1.0000x reference)
#include <cuda_runtime.h>
#include <math.h>
#include <stdint.h>

// ---------------------------------------------------------------------------
// 2-layer LSTM (T=1024, B=128, E=58, H=256) + Linear(256->33) + softplus.
//
// R11 vs R10: 512 threads (16 warps = 4/SMSP, was 2/SMSP). The R10 GEMM ran
// ~1.8x above the FFMA2 issue floor because 2 warps/SMSP cannot hide the
// 29-cyc LDS latency + rt=2 issue gaps. Decomposition: 8 k-groups x 2
// batch-half warps; per thread 8 cols x 2 batch = 8 f32x2 accs;
// 3 LDS.128 per 8 FFMA2. Everything else (flags, dup h history, x prefetch,
// Part aliasing) unchanged from R10.
// ---------------------------------------------------------------------------

namespace {
constexpr int TT = 1024;
constexpr int BB = 128;
constexpr int EE = 58;
constexpr int HH = 256;
constexpr int OO = 33;

constexpr int HT = 16;              // hidden units per CTA
constexpr int BT = 16;              // batch per CTA
constexpr int HS = HH / HT;         // 16 hidden slices
constexpr int BS = BB / BT;         // 8 batch slices
constexpr int NCTA = HS * BS;       // 128
constexpr int NTHR = 512;
}

// Scratch (static __device__: allocation-free per harness rules)
__device__ float2 g_y0[(size_t)TT * HH * BB];  // layer0 h, [t][h][b], (v,v) dup
__device__ float2 g_y1[(size_t)TT * HH * BB];  // layer1 h, [t][h][b], (v,v) dup
__device__ unsigned g_flags[2 * NCTA];

__global__ void reset_kernel() {
    int i = threadIdx.x;
    if (i < 2 * NCTA) g_flags[i] = 0u;
}

__device__ __forceinline__ void ffma2(uint64_t& d, uint64_t a, uint64_t b) {
    asm("fma.rn.f32x2 %0, %1, %2, %0;" : "+l"(d) : "l"(a), "l"(b));
}

__device__ __forceinline__ float fast_sigmoid(float x) {
    return __fdividef(1.f, 1.f + __expf(-x));
}
__device__ __forceinline__ float fast_tanh(float x) {
    float t = __expf(-2.f * fabsf(x));
    float r = __fdividef(1.f - t, 1.f + t);
    return copysignf(r, x);
}

// GEMM over k range [k0,k1): 8 cols x 2 batch per thread via f32x2.
// acc[cp][bi]: cp = col-pair 0..3 (cols jt*4+2cp%.., wB at +32), bi = batch.
__device__ __forceinline__ void gemm_range(const float* __restrict__ Ws,
                                           const float2* __restrict__ In2,
                                           int k0, int k1, int jt, int b2,
                                           uint64_t acc[4][2]) {
    const char* wp = (const char*)(Ws + (size_t)k0 * 64 + jt * 4);
    const char* ip = (const char*)(In2 + (size_t)k0 * 16 + b2);
    #pragma unroll 4
    for (int k = k0; k < k1; k++) {
        const ulonglong2 wA = *(const ulonglong2*)wp;          // cols jt*4..+3
        const ulonglong2 wB = *(const ulonglong2*)(wp + 128);  // cols 32+jt*4..+3
        const ulonglong2 ia = *(const ulonglong2*)ip;          // b2,b2+1 (dup)
        ffma2(acc[0][0], wA.x, ia.x); ffma2(acc[1][0], wA.y, ia.x);
        ffma2(acc[2][0], wB.x, ia.x); ffma2(acc[3][0], wB.y, ia.x);
        ffma2(acc[0][1], wA.x, ia.y); ffma2(acc[1][1], wA.y, ia.y);
        ffma2(acc[2][1], wB.x, ia.y); ffma2(acc[3][1], wB.y, ia.y);
        wp += 256;
        ip += 128;
    }
}

template<int LAYER>
__global__ void __launch_bounds__(NTHR, 1)
lstm_layer_kernel(const float* __restrict__ xin,   // LAYER0 only: x [T][B][E]
                  const float* __restrict__ W_ih,  // (4H, K1) row-major
                  const float* __restrict__ W_hh,  // (4H, H)  row-major
                  const float* __restrict__ b_ih,
                  const float* __restrict__ b_hh,
                  const float* __restrict__ h0,    // (B, H)
                  const float* __restrict__ c0,    // (B, H)
                  float* __restrict__ hn,          // (B, H)
                  float* __restrict__ cn)          // (B, H)
{
    constexpr int K1   = (LAYER == 0) ? EE : HH;
    constexpr int KTOT = K1 + HH;

    float2*       yout = (LAYER == 0) ? g_y0 : g_y1;   // own h history (dup)
    const float2* xdup = g_y0;                          // LAYER1 x source

    extern __shared__ float sm[];
    float*  Ws  = sm;                                   // [KTOT][64]
    float2* In2 = (float2*)(sm + (size_t)KTOT * 64);    // [KTOT][16] dup pairs
    // Part: 8 kg x 16 b x 64 cols = 32768 B. L1: alias onto In2 x-region
    // (exactly 256 rows x 128 B). L0: separate tail region.
    float* Part = (LAYER == 1) ? (float*)In2
                               : (float*)(In2 + (size_t)KTOT * 16);

    const int tid   = threadIdx.x;
    const int cta   = blockIdx.x;
    const int hsl   = cta & (HS - 1);
    const int bsl   = cta >> 4;
    const int hbase = hsl * HT;
    const int bbase = bsl * BT;

    // ---- stage weight slice once: Ws[k][gate*16+hh] ----
    for (int i = tid; i < KTOT * 64; i += NTHR) {
        int jl = i / KTOT;
        int k  = i - jl * KTOT;
        int gate = jl >> 4;
        int hh   = jl & 15;
        int row  = gate * HH + hbase + hh;
        float w = (k < K1) ? W_ih[row * K1 + k] : W_hh[row * HH + (k - K1)];
        Ws[(size_t)k * 64 + jl] = w;
    }

    // ---- GEMM thread mapping: 16 warps = 8 k-groups x 2 batch halves ----
    const int w     = tid >> 5;        // 0..15
    const int kg    = w >> 1;          // 0..7
    const int bhalf = w & 1;           // 0..1
    const int rr    = tid & 31;
    const int jt    = rr & 7;          // cols jt*4..+3 and 32+jt*4..+3
    const int b2    = bhalf * 8 + (rr >> 3) * 2;   // batches b2, b2+1
    const int kx0 = (K1 * kg) / 8;
    const int kx1 = (K1 * (kg + 1)) / 8;
    const int kh0 = K1 + kg * (HH / 8);
    const int kh1 = kh0 + HH / 8;

    // ---- dup-tile index map (h staging + L1 x staging): 4 uint4 each ----
    int    sIdx[4];
    size_t gIdx[4];
    #pragma unroll
    for (int m = 0; m < 4; m++) {
        int e = tid + m * NTHR;       // 0..2047
        int k = e >> 3;
        int bq = e & 7;
        sIdx[m] = k * 16 + bq * 2;                       // float2 idx in In2 rows
        gIdx[m] = (size_t)k * BB + bbase + bq * 2;       // float2 idx in y plane
    }

    // ---- L0 x scalar map: 2 elems per thread ----
    int  xsk[2], xsb[2], xgo[2];
    bool xok[2];
    if (LAYER == 0) {
        #pragma unroll
        for (int m = 0; m < 2; m++) {
            int idx = tid + m * NTHR;
            xok[m] = idx < EE * BT;
            int ii = xok[m] ? idx : 0;
            int b = ii / EE;
            int k = ii - b * EE;
            xsk[m] = k; xsb[m] = b;
            xgo[m] = (bbase + b) * EE + k;
        }
    }

    // ---- epilogue mapping (tid < 256 only) ----
    const bool epi = tid < 256;
    const int eb = (tid >> 4) & 15;
    const int eh = tid & 15;
    float bias0 = 0.f, bias1 = 0.f, bias2 = 0.f, bias3 = 0.f, cacc = 0.f;
    if (epi) {
        bias0 = b_ih[0 * HH + hbase + eh] + b_hh[0 * HH + hbase + eh];
        bias1 = b_ih[1 * HH + hbase + eh] + b_hh[1 * HH + hbase + eh];
        bias2 = b_ih[2 * HH + hbase + eh] + b_hh[2 * HH + hbase + eh];
        bias3 = b_ih[3 * HH + hbase + eh] + b_hh[3 * HH + hbase + eh];
        cacc  = c0[(bbase + eb) * HH + hbase + eh];
    }

    const unsigned* flg_grp = &g_flags[LAYER * NCTA + bsl * HS];
    unsigned* flg_self = &g_flags[LAYER * NCTA + cta];

    // ---- prologue x prefetch (t = 0) ----
    float xv[2];
    uint4 xr[4];
    if (LAYER == 0) {
        #pragma unroll
        for (int m = 0; m < 2; m++) xv[m] = xok[m] ? xin[xgo[m]] : 0.f;
    } else {
        #pragma unroll
        for (int m = 0; m < 4; m++)
            xr[m] = *(const uint4*)&xdup[gIdx[m]];
    }

    __syncthreads();

    for (int t = 0; t < TT; t++) {
        // ---- store x_t (from regs) into In2 x-region ----
        if (LAYER == 0) {
            #pragma unroll
            for (int m = 0; m < 2; m++)
                if (xok[m]) In2[xsk[m] * 16 + xsb[m]] = make_float2(xv[m], xv[m]);
        } else {
            #pragma unroll
            for (int m = 0; m < 4; m++)
                *(uint4*)&In2[sIdx[m]] = xr[m];
        }
        __syncthreads();   // S1

        // ---- prefetch x_{t+1} into regs (completes under the GEMMs) ----
        if (t + 1 < TT) {
            if (LAYER == 0) {
                const float* xt = xin + (size_t)(t + 1) * BB * EE;
                #pragma unroll
                for (int m = 0; m < 2; m++) if (xok[m]) xv[m] = xt[xgo[m]];
            } else {
                const float2* xp = xdup + (size_t)(t + 1) * HH * BB;
                #pragma unroll
                for (int m = 0; m < 4; m++) xr[m] = *(const uint4*)&xp[gIdx[m]];
            }
        }

        // ---- x-part GEMM (shadows peers' publish latency) ----
        uint64_t acc[4][2] = {{0,0},{0,0},{0,0},{0,0}};
        gemm_range(Ws, In2, kx0, kx1, jt, b2, acc);

        // ---- group-local barrier: 16 producers of our batch slice ----
        if (t > 0) {
            if (tid < HS) {
                const unsigned* fp = flg_grp + tid;
                unsigned v;
                do {
                    asm volatile("ld.acquire.gpu.global.u32 %0, [%1];" : "=r"(v) : "l"(fp));
                } while (v < (unsigned)t);
            }
            __syncthreads();   // S2
        }

        // ---- stage h_{t-1} (already dup in global) ----
        if (t == 0) {
            #pragma unroll
            for (int m = 0; m < 8; m++) {
                int idx = tid + m * NTHR;
                int k = idx >> 4;
                int b = idx & 15;
                float v = h0[(bbase + b) * HH + k];
                In2[(K1 + k) * 16 + b] = make_float2(v, v);
            }
        } else {
            const float2* hp = yout + (size_t)(t - 1) * HH * BB;
            #pragma unroll
            for (int m = 0; m < 4; m++) {
                uint4 v = *(const uint4*)&hp[gIdx[m]];
                *(uint4*)&In2[K1 * 16 + sIdx[m]] = v;
            }
        }
        __syncthreads();   // S3

        // ---- h-part GEMM ----
        gemm_range(Ws, In2, kh0, kh1, jt, b2, acc);

        // ---- write partials (aliases In2 x-region for LAYER1 — safe:
        //      x-GEMM done before S3, next x-store is after S5) ----
        {
            float* pb = Part + kg * 1024 + jt * 4;
            #pragma unroll
            for (int bi = 0; bi < 2; bi++) {
                ulonglong2 vA; vA.x = acc[0][bi]; vA.y = acc[1][bi];
                ulonglong2 vB; vB.x = acc[2][bi]; vB.y = acc[3][bi];
                *(ulonglong2*)(pb + (b2 + bi) * 64)      = vA;
                *(ulonglong2*)(pb + (b2 + bi) * 64 + 32) = vB;
            }
        }
        __syncthreads();   // S4

        // ---- epilogue: reduce 8 k-groups, gate math, update c ----
        float hv = 0.f;
        if (epi) {
            float s0 = bias0, s1 = bias1, s2 = bias2, s3 = bias3;
            #pragma unroll
            for (int p = 0; p < 8; p++) {
                const float* pp = Part + p * 1024 + eb * 64;
                s0 += pp[ 0 + eh];
                s1 += pp[16 + eh];
                s2 += pp[32 + eh];
                s3 += pp[48 + eh];
            }
            const float ig = fast_sigmoid(s0);
            const float fg = fast_sigmoid(s1);
            const float gt = fast_tanh(s2);
            const float og = fast_sigmoid(s3);
            cacc = fg * cacc + ig * gt;
            hv = og * fast_tanh(cacc);

            yout[(size_t)t * HH * BB + (hbase + eh) * BB + (bbase + eb)] =
                make_float2(hv, hv);
            if (t == TT - 1) {
                hn[(bbase + eb) * HH + hbase + eh] = hv;
                cn[(bbase + eb) * HH + hbase + eh] = cacc;
            }
        }

        __syncthreads();   // S5: all hv stores + Part reads done
        if (tid == 0) {
            asm volatile("st.release.gpu.global.u32 [%0], %1;"
                         :: "l"(flg_self), "r"((unsigned)(t + 1)) : "memory");
        }
    }
}

// Final projection + softplus: out[t][b][o] = softplus(y1[t]·W_out^T + b_out)
__global__ void __launch_bounds__(128, 4)
proj_kernel(const float* __restrict__ W_out,  // (33, 256)
            const float* __restrict__ b_out,  // (33,)
            float* __restrict__ out)          // [T][B][33]
{
    __shared__ float Wsm[HH * OO];   // [k][o]
    const int t = blockIdx.x;
    const int b = threadIdx.x;       // 0..127

    for (int i = b; i < HH * OO; i += 128) {
        int k = i / OO;
        int o = i - k * OO;
        Wsm[k * OO + o] = W_out[o * HH + k];
    }
    __syncthreads();

    const float2* y = g_y1 + (size_t)t * HH * BB;   // [H][B] dup
    float acc[OO];
    #pragma unroll
    for (int o = 0; o < OO; o++) acc[o] = b_out[o];

    #pragma unroll 4
    for (int k = 0; k < HH; k++) {
        const float yv = y[k * BB + b].x;
        const float* wr = &Wsm[k * OO];
        #pragma unroll
        for (int o = 0; o < OO; o++) acc[o] += yv * wr[o];
    }

    float* op = out + (size_t)t * BB * OO + b * OO;
    #pragma unroll
    for (int o = 0; o < OO; o++) {
        const float x = acc[o];
        op[o] = fmaxf(x, 0.f) + log1pf(__expf(-fabsf(x)));  // stable softplus
    }
}

extern "C" void kernel_launch(void* const* d_in, const int* in_sizes, int n_in,
                              void* d_out, int out_size) {
    const float* x     = (const float*)d_in[0];
    const float* h0    = (const float*)d_in[1];   // (2,B,H)
    const float* c0    = (const float*)d_in[2];   // (2,B,H)
    const float* W_ih0 = (const float*)d_in[3];
    const float* W_hh0 = (const float*)d_in[4];
    const float* b_ih0 = (const float*)d_in[5];
    const float* b_hh0 = (const float*)d_in[6];
    const float* W_ih1 = (const float*)d_in[7];
    const float* W_hh1 = (const float*)d_in[8];
    const float* b_ih1 = (const float*)d_in[9];
    const float* b_hh1 = (const float*)d_in[10];
    const float* W_out = (const float*)d_in[11];
    const float* b_out = (const float*)d_in[12];

    float* out = (float*)d_out;
    float* hn  = out + (size_t)TT * BB * OO;   // (2,B,H)
    float* cn  = hn + 2 * BB * HH;             // (2,B,H)

    constexpr int KTOT0 = EE + HH;   // 314
    constexpr int KTOT1 = HH + HH;   // 512
    // L0: Ws + In2 + separate Part; L1: Ws + In2 (Part aliased)
    const int smem0 = KTOT0 * 64 * 4 + KTOT0 * 16 * 8 + 8 * 1024 * 4;  // 153,344
    const int smem1 = KTOT1 * 64 * 4 + KTOT1 * 16 * 8;                 // 196,608

    cudaFuncSetAttribute((const void*)lstm_layer_kernel<0>,
                         cudaFuncAttributeMaxDynamicSharedMemorySize, smem0);
    cudaFuncSetAttribute((const void*)lstm_layer_kernel<1>,
                         cudaFuncAttributeMaxDynamicSharedMemorySize, smem1);

    reset_kernel<<<1, 256>>>();

    lstm_layer_kernel<0><<<NCTA, NTHR, smem0>>>(
        x, W_ih0, W_hh0, b_ih0, b_hh0,
        h0 + 0 * BB * HH, c0 + 0 * BB * HH,
        hn + 0 * BB * HH, cn + 0 * BB * HH);

    lstm_layer_kernel<1><<<NCTA, NTHR, smem1>>>(
        nullptr, W_ih1, W_hh1, b_ih1, b_hh1,
        h0 + 1 * BB * HH, c0 + 1 * BB * HH,
        hn + 1 * BB * HH, cn + 1 * BB * HH);

    proj_kernel<<<TT, 128>>>(W_out, b_out, out);
}

// round 12
// speedup vs baseline: 1.1181x; 1.1181x over previous
#include <cuda_runtime.h>
#include <math.h>
#include <stdint.h>

// ---------------------------------------------------------------------------
// 2-layer LSTM (T=1024, B=128, E=58, H=256) + Linear(256->33) + softplus.
//
// R12 vs R10 (R11 reverted):
//  * k-paired FFMA2: acc pairs over (even k, odd k); weights and inputs both
//    stored as k-pairs (8B), NO input duplication. 6 LDS.128 per 32 FFMA2
//    (was 8), h-staging bytes halved, In smem halved.
//  * x region double-buffered -> barrier S1 removed (4 barriers/step);
//    x_{t+1} LDG issued at step top, STS under the h-GEMM shadow.
//  * Part buffer separate (no aliasing) with row stride 80 floats ->
//    conflict-free epilogue reads.
// ---------------------------------------------------------------------------

namespace {
constexpr int TT = 1024;
constexpr int BB = 128;
constexpr int EE = 58;
constexpr int HH = 256;
constexpr int OO = 33;

constexpr int HT = 16;              // hidden units per CTA
constexpr int BT = 16;              // batch per CTA
constexpr int HS = HH / HT;         // 16 hidden slices
constexpr int BS = BB / BT;         // 8 batch slices
constexpr int NCTA = HS * BS;       // 128
constexpr int NTHR = 256;
constexpr int HP = HH / 2;          // 128 h k-pairs
constexpr int PJ = 80;              // Part row stride (floats): 320B = 64 mod 128 -> conflict-free
}

// Scratch (static __device__: allocation-free per harness rules)
__device__ float2 g_y0[(size_t)TT * HP * BB];  // [t][hpair][b] = (h_2k, h_2k+1)
__device__ float2 g_y1[(size_t)TT * HP * BB];
__device__ unsigned g_flags[2 * NCTA];

__global__ void reset_kernel() {
    int i = threadIdx.x;
    if (i < 2 * NCTA) g_flags[i] = 0u;
}

__device__ __forceinline__ void ffma2(uint64_t& d, uint64_t a, uint64_t b) {
    asm("fma.rn.f32x2 %0, %1, %2, %0;" : "+l"(d) : "l"(a), "l"(b));
}

__device__ __forceinline__ float fast_sigmoid(float x) {
    return __fdividef(1.f, 1.f + __expf(-x));
}
__device__ __forceinline__ float fast_tanh(float x) {
    float t = __expf(-2.f * fabsf(x));
    float r = __fdividef(1.f - t, 1.f + t);
    return copysignf(r, x);
}

// k-paired GEMM over pair range [p0,p1) relative to the given bases.
// Thread tile: 8 cols (jt*4..+3 and 32+jt*4..+3) x 4 batches (bt*4..+3).
// acc[c][b] holds (even-k partial, odd-k partial).
__device__ __forceinline__ void gemm_pairs(const float2* __restrict__ Wb,  // [*][64]
                                           const float2* __restrict__ Ib,  // [*][16]
                                           int p0, int p1, int jt, int bt,
                                           uint64_t acc[8][4]) {
    const char* wp = (const char*)(Wb + (size_t)p0 * 64 + jt * 4);
    const char* ip = (const char*)(Ib + (size_t)p0 * 16 + bt * 4);
    #pragma unroll 2
    for (int k = p0; k < p1; k++) {
        const ulonglong2 w0 = *(const ulonglong2*)(wp);        // cols j0, j0+1
        const ulonglong2 w1 = *(const ulonglong2*)(wp + 16);   // cols j0+2, j0+3
        const ulonglong2 w2 = *(const ulonglong2*)(wp + 256);  // cols 32+j0, +1
        const ulonglong2 w3 = *(const ulonglong2*)(wp + 272);  // cols 32+j0+2, +3
        const ulonglong2 i0 = *(const ulonglong2*)(ip);        // b0, b1
        const ulonglong2 i1 = *(const ulonglong2*)(ip + 16);   // b2, b3
        ffma2(acc[0][0], w0.x, i0.x); ffma2(acc[1][0], w0.y, i0.x);
        ffma2(acc[2][0], w1.x, i0.x); ffma2(acc[3][0], w1.y, i0.x);
        ffma2(acc[4][0], w2.x, i0.x); ffma2(acc[5][0], w2.y, i0.x);
        ffma2(acc[6][0], w3.x, i0.x); ffma2(acc[7][0], w3.y, i0.x);
        ffma2(acc[0][1], w0.x, i0.y); ffma2(acc[1][1], w0.y, i0.y);
        ffma2(acc[2][1], w1.x, i0.y); ffma2(acc[3][1], w1.y, i0.y);
        ffma2(acc[4][1], w2.x, i0.y); ffma2(acc[5][1], w2.y, i0.y);
        ffma2(acc[6][1], w3.x, i0.y); ffma2(acc[7][1], w3.y, i0.y);
        ffma2(acc[0][2], w0.x, i1.x); ffma2(acc[1][2], w0.y, i1.x);
        ffma2(acc[2][2], w1.x, i1.x); ffma2(acc[3][2], w1.y, i1.x);
        ffma2(acc[4][2], w2.x, i1.x); ffma2(acc[5][2], w2.y, i1.x);
        ffma2(acc[6][2], w3.x, i1.x); ffma2(acc[7][2], w3.y, i1.x);
        ffma2(acc[0][3], w0.x, i1.y); ffma2(acc[1][3], w0.y, i1.y);
        ffma2(acc[2][3], w1.x, i1.y); ffma2(acc[3][3], w1.y, i1.y);
        ffma2(acc[4][3], w2.x, i1.y); ffma2(acc[5][3], w2.y, i1.y);
        ffma2(acc[6][3], w3.x, i1.y); ffma2(acc[7][3], w3.y, i1.y);
        wp += 512;   // 64 float2
        ip += 128;   // 16 float2
    }
}

template<int LAYER>
__global__ void __launch_bounds__(NTHR, 1)
lstm_layer_kernel(const float* __restrict__ xin,   // LAYER0 only: x [T][B][E]
                  const float* __restrict__ W_ih,  // (4H, K1) row-major
                  const float* __restrict__ W_hh,  // (4H, H)  row-major
                  const float* __restrict__ b_ih,
                  const float* __restrict__ b_hh,
                  const float* __restrict__ h0,    // (B, H)
                  const float* __restrict__ c0,    // (B, H)
                  float* __restrict__ hn,          // (B, H)
                  float* __restrict__ cn)          // (B, H)
{
    constexpr int K1 = (LAYER == 0) ? EE : HH;
    constexpr int XP = K1 / 2;        // x k-pairs (29 or 128)
    constexpr int KP = XP + HP;       // total k-pairs

    float2*       yout = (LAYER == 0) ? g_y0 : g_y1;   // own h history (paired)
    const float2* xsrc2 = g_y0;                         // LAYER1 x source

    extern __shared__ float2 smp[];
    float2* Wp   = smp;                                  // [KP][64] k-pair weights
    float2* Inh  = Wp + (size_t)KP * 64;                 // [HP][16] h pairs
    float2* Xb   = Inh + (size_t)HP * 16;                // 2 x [XP][16]
    float*  Part = (float*)(Xb + (size_t)2 * XP * 16);   // [8][16][PJ]

    const int tid   = threadIdx.x;
    const int cta   = blockIdx.x;
    const int hsl   = cta & (HS - 1);
    const int bsl   = cta >> 4;
    const int hbase = hsl * HT;
    const int bbase = bsl * BT;

    // ---- stage weight slice once as k-pairs: Wp[kp][gate*16+hh] ----
    for (int i = tid; i < KP * 64; i += NTHR) {
        int jl = i / KP;
        int kp = i - jl * KP;
        int gate = jl >> 4;
        int hh   = jl & 15;
        int row  = gate * HH + hbase + hh;
        float2 w;
        if (kp < XP) w = *((const float2*)(W_ih + (size_t)row * K1) + kp);
        else         w = *((const float2*)(W_hh + (size_t)row * HH) + (kp - XP));
        Wp[(size_t)kp * 64 + jl] = w;
    }

    // ---- GEMM thread mapping (R10 shape): warp == k-group ----
    const int kg = tid >> 5;          // 0..7
    const int rr = tid & 31;
    const int bt = rr >> 3;           // 0..3
    const int jt = rr & 7;            // 0..7
    const int xp0 = (XP * kg) >> 3;
    const int xp1 = (XP * (kg + 1)) >> 3;
    const int hp0 = kg * (HP / 8);
    const int hp1 = hp0 + HP / 8;

    // ---- h staging map: 4 uint4 per thread (128 rows x 8 batch-pairs) ----
    int    sIdx[4];
    size_t gIdx[4];
    #pragma unroll
    for (int m = 0; m < 4; m++) {
        int e = tid + m * NTHR;       // 0..1023
        int kp = e >> 3;              // 0..127
        int bq = e & 7;
        sIdx[m] = kp * 16 + bq * 2;
        gIdx[m] = (size_t)kp * BB + bbase + bq * 2;
    }

    // ---- L0 x map: 2 float2 per thread (29 rows x 16 batches = 464) ----
    int  xsi[2], xgo[2];
    bool xok[2];
    if (LAYER == 0) {
        #pragma unroll
        for (int m = 0; m < 2; m++) {
            int idx = tid + m * NTHR;
            xok[m] = idx < XP * 16;
            int ii = xok[m] ? idx : 0;
            int kp = ii >> 4;
            int b  = ii & 15;
            xsi[m] = kp * 16 + b;
            xgo[m] = ((bbase + b) * EE + 2 * kp) >> 1;   // float2 index
        }
    }

    // ---- epilogue mapping: (eb, eh) owns one (b, h) cell ----
    const int eb = tid >> 4;
    const int eh = tid & 15;
    const float bias0 = b_ih[0 * HH + hbase + eh] + b_hh[0 * HH + hbase + eh];
    const float bias1 = b_ih[1 * HH + hbase + eh] + b_hh[1 * HH + hbase + eh];
    const float bias2 = b_ih[2 * HH + hbase + eh] + b_hh[2 * HH + hbase + eh];
    const float bias3 = b_ih[3 * HH + hbase + eh] + b_hh[3 * HH + hbase + eh];
    float cacc = c0[(bbase + eb) * HH + hbase + eh];

    const unsigned* flg_grp = &g_flags[LAYER * NCTA + bsl * HS];
    unsigned* flg_self = &g_flags[LAYER * NCTA + cta];

    // ---- prologue: stage x_0 into Xb[0] and h0 into Inh ----
    if (LAYER == 0) {
        #pragma unroll
        for (int m = 0; m < 2; m++)
            if (xok[m]) Xb[xsi[m]] = ((const float2*)xin)[xgo[m]];
    } else {
        #pragma unroll
        for (int m = 0; m < 4; m++)
            *(uint4*)&Xb[sIdx[m]] = *(const uint4*)&xsrc2[gIdx[m]];
    }
    #pragma unroll
    for (int m = 0; m < 8; m++) {
        int e = tid + m * NTHR;       // 0..2047
        int kp = e >> 4;              // 0..127
        int b  = e & 15;
        Inh[kp * 16 + b] = ((const float2*)h0)[(size_t)(bbase + b) * HP + kp];
    }
    __syncthreads();

    for (int t = 0; t < TT; t++) {
        const float2* Xcur = Xb + (size_t)(t & 1) * XP * 16;
        float2* Xnxt = Xb + (size_t)(~t & 1) * XP * 16;

        // ---- issue x_{t+1} prefetch (lands during the two GEMMs) ----
        float2 xv2[2];
        uint4  xr[4];
        if (t + 1 < TT) {
            if (LAYER == 0) {
                const float2* xt = (const float2*)xin + (size_t)(t + 1) * (BB * EE / 2);
                #pragma unroll
                for (int m = 0; m < 2; m++) if (xok[m]) xv2[m] = xt[xgo[m]];
            } else {
                const float2* xp = xsrc2 + (size_t)(t + 1) * HP * BB;
                #pragma unroll
                for (int m = 0; m < 4; m++) xr[m] = *(const uint4*)&xp[gIdx[m]];
            }
        }

        // ---- x-part GEMM (shadows peers' publish latency) ----
        uint64_t acc[8][4] = {};
        gemm_pairs(Wp, Xcur, xp0, xp1, jt, bt, acc);

        // ---- group-local barrier: 16 producers of our batch slice ----
        if (t > 0) {
            if (tid < HS) {
                const unsigned* fp = flg_grp + tid;
                unsigned v;
                do {
                    asm volatile("ld.acquire.gpu.global.u32 %0, [%1];" : "=r"(v) : "l"(fp));
                } while (v < (unsigned)t);
            }
            __syncthreads();   // S2

            // ---- stage h_{t-1} (paired in global) ----
            const float2* hp = yout + (size_t)(t - 1) * HP * BB;
            #pragma unroll
            for (int m = 0; m < 4; m++)
                *(uint4*)&Inh[sIdx[m]] = *(const uint4*)&hp[gIdx[m]];
        }
        __syncthreads();   // S3

        // ---- h-part GEMM ----
        gemm_pairs(Wp + (size_t)XP * 64, Inh, hp0, hp1, jt, bt, acc);

        // ---- store x_{t+1} into the alternate buffer (off critical path) ----
        if (t + 1 < TT) {
            if (LAYER == 0) {
                #pragma unroll
                for (int m = 0; m < 2; m++) if (xok[m]) Xnxt[xsi[m]] = xv2[m];
            } else {
                #pragma unroll
                for (int m = 0; m < 4; m++) *(uint4*)&Xnxt[sIdx[m]] = xr[m];
            }
        }

        // ---- horizontal add + Part write (conflict-free stride 80) ----
        {
            float* pb = Part + kg * (BT * PJ) + jt * 4;
            #pragma unroll
            for (int bi = 0; bi < 4; bi++) {
                union { uint64_t u; float2 f; } c0u, c1u, c2u, c3u;
                float4 vA, vB;
                c0u.u = acc[0][bi]; c1u.u = acc[1][bi];
                c2u.u = acc[2][bi]; c3u.u = acc[3][bi];
                vA.x = c0u.f.x + c0u.f.y; vA.y = c1u.f.x + c1u.f.y;
                vA.z = c2u.f.x + c2u.f.y; vA.w = c3u.f.x + c3u.f.y;
                c0u.u = acc[4][bi]; c1u.u = acc[5][bi];
                c2u.u = acc[6][bi]; c3u.u = acc[7][bi];
                vB.x = c0u.f.x + c0u.f.y; vB.y = c1u.f.x + c1u.f.y;
                vB.z = c2u.f.x + c2u.f.y; vB.w = c3u.f.x + c3u.f.y;
                *(float4*)(pb + (bt * 4 + bi) * PJ)      = vA;
                *(float4*)(pb + (bt * 4 + bi) * PJ + 32) = vB;
            }
        }
        __syncthreads();   // S4

        // ---- epilogue: reduce 8 k-groups, gate math, update c ----
        float s0 = bias0, s1 = bias1, s2 = bias2, s3 = bias3;
        #pragma unroll
        for (int p = 0; p < 8; p++) {
            const float* pp = Part + p * (BT * PJ) + eb * PJ;
            s0 += pp[ 0 + eh];
            s1 += pp[16 + eh];
            s2 += pp[32 + eh];
            s3 += pp[48 + eh];
        }
        const float ig = fast_sigmoid(s0);
        const float fg = fast_sigmoid(s1);
        const float gt = fast_tanh(s2);
        const float og = fast_sigmoid(s3);
        cacc = fg * cacc + ig * gt;
        const float hv = og * fast_tanh(cacc);

        // pair with neighbor (eh, eh+1) and write float2 history
        const float hv1 = __shfl_down_sync(0xffffffffu, hv, 1);
        if (!(eh & 1)) {
            yout[(size_t)t * HP * BB + ((hbase + eh) >> 1) * BB + (bbase + eb)] =
                make_float2(hv, hv1);
        }
        if (t == TT - 1) {
            hn[(bbase + eb) * HH + hbase + eh] = hv;
            cn[(bbase + eb) * HH + hbase + eh] = cacc;
        }

        __syncthreads();   // S5: all y stores + Part reads done
        if (tid == 0) {
            asm volatile("st.release.gpu.global.u32 [%0], %1;"
                         :: "l"(flg_self), "r"((unsigned)(t + 1)) : "memory");
        }
    }
}

// Final projection + softplus: out[t][b][o] = softplus(y1[t]·W_out^T + b_out)
__global__ void __launch_bounds__(128, 4)
proj_kernel(const float* __restrict__ W_out,  // (33, 256)
            const float* __restrict__ b_out,  // (33,)
            float* __restrict__ out)          // [T][B][33]
{
    __shared__ float Wsm[HH * OO];   // [k][o]
    const int t = blockIdx.x;
    const int b = threadIdx.x;       // 0..127

    for (int i = b; i < HH * OO; i += 128) {
        int k = i / OO;
        int o = i - k * OO;
        Wsm[k * OO + o] = W_out[o * HH + k];
    }
    __syncthreads();

    const float2* y = g_y1 + (size_t)t * HP * BB;   // [hpair][B]
    float acc[OO];
    #pragma unroll
    for (int o = 0; o < OO; o++) acc[o] = b_out[o];

    #pragma unroll 2
    for (int kp = 0; kp < HP; kp++) {
        const float2 v = y[kp * BB + b];            // coalesced across the warp
        const float* w0 = &Wsm[(2 * kp) * OO];
        const float* w1 = &Wsm[(2 * kp + 1) * OO];
        #pragma unroll
        for (int o = 0; o < OO; o++) acc[o] += v.x * w0[o] + v.y * w1[o];
    }

    float* op = out + (size_t)t * BB * OO + b * OO;
    #pragma unroll
    for (int o = 0; o < OO; o++) {
        const float x = acc[o];
        op[o] = fmaxf(x, 0.f) + log1pf(__expf(-fabsf(x)));  // stable softplus
    }
}

extern "C" void kernel_launch(void* const* d_in, const int* in_sizes, int n_in,
                              void* d_out, int out_size) {
    const float* x     = (const float*)d_in[0];
    const float* h0    = (const float*)d_in[1];   // (2,B,H)
    const float* c0    = (const float*)d_in[2];   // (2,B,H)
    const float* W_ih0 = (const float*)d_in[3];
    const float* W_hh0 = (const float*)d_in[4];
    const float* b_ih0 = (const float*)d_in[5];
    const float* b_hh0 = (const float*)d_in[6];
    const float* W_ih1 = (const float*)d_in[7];
    const float* W_hh1 = (const float*)d_in[8];
    const float* b_ih1 = (const float*)d_in[9];
    const float* b_hh1 = (const float*)d_in[10];
    const float* W_out = (const float*)d_in[11];
    const float* b_out = (const float*)d_in[12];

    float* out = (float*)d_out;
    float* hn  = out + (size_t)TT * BB * OO;   // (2,B,H)
    float* cn  = hn + 2 * BB * HH;             // (2,B,H)

    // smem bytes: Wp[KP][64]*8 + Inh[128][16]*8 + Xb 2*[XP][16]*8 + Part 8*16*80*4
    constexpr int XP0 = EE / 2, KP0 = XP0 + HP;    // 29, 157
    constexpr int XP1 = HH / 2, KP1 = XP1 + HP;    // 128, 256
    const int smem0 = KP0 * 64 * 8 + HP * 16 * 8 + 2 * XP0 * 16 * 8 + 8 * 16 * PJ * 4; // 145,152
    const int smem1 = KP1 * 64 * 8 + HP * 16 * 8 + 2 * XP1 * 16 * 8 + 8 * 16 * PJ * 4; // 221,184

    cudaFuncSetAttribute((const void*)lstm_layer_kernel<0>,
                         cudaFuncAttributeMaxDynamicSharedMemorySize, smem0);
    cudaFuncSetAttribute((const void*)lstm_layer_kernel<1>,
                         cudaFuncAttributeMaxDynamicSharedMemorySize, smem1);

    reset_kernel<<<1, 256>>>();

    lstm_layer_kernel<0><<<NCTA, NTHR, smem0>>>(
        x, W_ih0, W_hh0, b_ih0, b_hh0,
        h0 + 0 * BB * HH, c0 + 0 * BB * HH,
        hn + 0 * BB * HH, cn + 0 * BB * HH);

    lstm_layer_kernel<1><<<NCTA, NTHR, smem1>>>(
        nullptr, W_ih1, W_hh1, b_ih1, b_hh1,
        h0 + 1 * BB * HH, c0 + 1 * BB * HH,
        hn + 1 * BB * HH, cn + 1 * BB * HH);

    proj_kernel<<<TT, 128>>>(W_out, b_out, out);
}

// round 13
// speedup vs baseline: 1.3403x; 1.1987x over previous
#include <cuda_runtime.h>
#include <math.h>
#include <stdint.h>

// ---------------------------------------------------------------------------
// 2-layer LSTM (T=1024, B=128, E=58, H=256) + Linear(256->33) + softplus.
//
// R13: single fused persistent kernel, both layers interleaved per slot:
//   slot t = [stage y0(t-1)] -> L0 hGEMM(t) + L1 xGEMM(t-1)
//            -> [stage y1(t-2)] -> L1 hGEMM(t-1) -> epi0 -> epi1
// Every cross-CTA dependency is >= half a slot old -> flag polls are instant
// and staging LDGs are fully shadowed. L0's x-projection precomputed by a
// parallel kernel (xp0, biases folded). Weights (Whh0 + Wih1 + Whh1) as
// f32x2 k-pairs in smem: 64K+128K; one shared In buffer (16K) + Part (17K).
// GEMM: 4 kgroups x 2 batch-half warps, 4 cols x 4 batches/thread,
// 16 f32x2 accs/layer, 4 LDS.128 per 16 FFMA2, broadcast lane map.
// ---------------------------------------------------------------------------

namespace {
constexpr int TT = 1024;
constexpr int BB = 128;
constexpr int EE = 58;
constexpr int HH = 256;
constexpr int OO = 33;

constexpr int HT = 16;             // hidden units per CTA
constexpr int BT = 16;             // batch per CTA
constexpr int HS = HH / HT;        // 16 hidden slices
constexpr int NCTA = 128;          // 16 x 8
constexpr int NTHR = 256;
constexpr int HP = HH / 2;         // 128 k-pairs
constexpr int PJ = 68;             // Part row stride (floats), 16B-aligned rows
}

// Scratch (static __device__: allocation-free per harness rules)
__device__ float2 g_y0[(size_t)TT * HP * BB];   // [t][hpair][b]
__device__ float2 g_y1[(size_t)TT * HP * BB];
__device__ float  g_xp0[(size_t)TT * BB * HH * 4];  // [t][b][h][gate]
__device__ unsigned g_flags[2 * NCTA];

__global__ void reset_kernel() {
    int i = threadIdx.x;
    if (i < 2 * NCTA) g_flags[i] = 0u;
}

__device__ __forceinline__ void ffma2(uint64_t& d, uint64_t a, uint64_t b) {
    asm("fma.rn.f32x2 %0, %1, %2, %0;" : "+l"(d) : "l"(a), "l"(b));
}
__device__ __forceinline__ float fast_sigmoid(float x) {
    return __fdividef(1.f, 1.f + __expf(-x));
}
__device__ __forceinline__ float fast_tanh(float x) {
    float t = __expf(-2.f * fabsf(x));
    float r = __fdividef(1.f - t, 1.f + t);
    return copysignf(r, x);
}

// ---------------------------------------------------------------------------
// xp0 precompute: xp0[t][b][h][g] = sum_e x[t][b][e]*W_ih0[g*H+h][e] + biases
// grid (TT, 8, 2): CTA = (t, 32-h slice, 64-b slice), 256 threads.
// ---------------------------------------------------------------------------
__global__ void __launch_bounds__(256)
xp0_kernel(const float* __restrict__ x,       // [T][B][E]
           const float* __restrict__ W_ih0,   // [4H][E]
           const float* __restrict__ b_ih0,
           const float* __restrict__ b_hh0) {
    __shared__ float xs[64][EE];
    __shared__ float ws[4][32][EE];
    __shared__ float bs[4][32];
    const int t = blockIdx.x;
    const int hbase = blockIdx.y * 32;
    const int bbase = blockIdx.z * 64;
    const int tid = threadIdx.x;

    for (int i = tid; i < 64 * EE; i += 256) {
        int b = i / EE, e = i - b * EE;
        xs[b][e] = x[((size_t)t * BB + bbase + b) * EE + e];
    }
    for (int i = tid; i < 4 * 32 * EE; i += 256) {
        int e = i % EE; int r = i / EE; int g = r >> 5, hh = r & 31;
        ws[g][hh][e] = W_ih0[(size_t)(g * HH + hbase + hh) * EE + e];
    }
    if (tid < 128) {
        int g = tid >> 5, hh = tid & 31;
        bs[g][hh] = b_ih0[g * HH + hbase + hh] + b_hh0[g * HH + hbase + hh];
    }
    __syncthreads();

    const int bb = tid >> 3;      // 0..31 -> batches bb*2, bb*2+1
    const int hq = tid & 7;       // 0..7  -> h = hq*4 .. +3
    float acc[2][4][4] = {};
    for (int e = 0; e < EE; e++) {
        float x0 = xs[bb * 2][e], x1 = xs[bb * 2 + 1][e];
        #pragma unroll
        for (int h = 0; h < 4; h++)
            #pragma unroll
            for (int g = 0; g < 4; g++) {
                float w = ws[g][hq * 4 + h][e];
                acc[0][h][g] += x0 * w;
                acc[1][h][g] += x1 * w;
            }
    }
    #pragma unroll
    for (int bi = 0; bi < 2; bi++)
        #pragma unroll
        for (int h = 0; h < 4; h++) {
            float4 v;
            v.x = acc[bi][h][0] + bs[0][hq * 4 + h];
            v.y = acc[bi][h][1] + bs[1][hq * 4 + h];
            v.z = acc[bi][h][2] + bs[2][hq * 4 + h];
            v.w = acc[bi][h][3] + bs[3][hq * 4 + h];
            *(float4*)&g_xp0[(((size_t)t * BB + bbase + bb * 2 + bi) * HH
                              + hbase + hq * 4 + h) * 4] = v;
        }
}

// 32 k-pairs GEMM: 4 cols x 4 batches per thread. Wb/Ab pre-offset to this
// warp's (kg, jt, b2). acc[i][bi] = f32x2 (even-k, odd-k) partials.
__device__ __forceinline__ void gemm32(const float2* __restrict__ Wb,
                                       const float2* __restrict__ Ab,
                                       uint64_t acc[4][4]) {
    const char* wp = (const char*)Wb;
    const char* ip = (const char*)Ab;
    #pragma unroll 4
    for (int k = 0; k < 32; k++) {
        const ulonglong2 w01 = *(const ulonglong2*)(wp);        // cols j0,j0+1
        const ulonglong2 w23 = *(const ulonglong2*)(wp + 16);   // cols j0+2,+3
        const ulonglong2 i01 = *(const ulonglong2*)(ip);        // b2, b2+1
        const ulonglong2 i23 = *(const ulonglong2*)(ip + 16);   // b2+2, b2+3
        ffma2(acc[0][0], w01.x, i01.x); ffma2(acc[1][0], w01.y, i01.x);
        ffma2(acc[2][0], w23.x, i01.x); ffma2(acc[3][0], w23.y, i01.x);
        ffma2(acc[0][1], w01.x, i01.y); ffma2(acc[1][1], w01.y, i01.y);
        ffma2(acc[2][1], w23.x, i01.y); ffma2(acc[3][1], w23.y, i01.y);
        ffma2(acc[0][2], w01.x, i23.x); ffma2(acc[1][2], w01.y, i23.x);
        ffma2(acc[2][2], w23.x, i23.x); ffma2(acc[3][2], w23.y, i23.x);
        ffma2(acc[0][3], w01.x, i23.y); ffma2(acc[1][3], w01.y, i23.y);
        ffma2(acc[2][3], w23.x, i23.y); ffma2(acc[3][3], w23.y, i23.y);
        wp += 512;   // 64 float2 per k-pair row
        ip += 128;   // 16 float2 per k-pair row
    }
}

__global__ void __launch_bounds__(NTHR, 1)
lstm_fused_kernel(const float* __restrict__ W_hh0,  // (4H, H)
                  const float* __restrict__ W_ih1,  // (4H, H)
                  const float* __restrict__ W_hh1,  // (4H, H)
                  const float* __restrict__ b_ih1,
                  const float* __restrict__ b_hh1,
                  const float* __restrict__ h0,     // (2, B, H)
                  const float* __restrict__ c0,     // (2, B, H)
                  float* __restrict__ hn,           // (2, B, H)
                  float* __restrict__ cn)           // (2, B, H)
{
    extern __shared__ float2 smp[];
    float2* Wp0 = smp;                      // [128][64]  W_hh0 k-pairs
    float2* Wp1 = Wp0 + 128 * 64;           // [256][64]  W_ih1 | W_hh1 k-pairs
    float2* A   = Wp1 + 256 * 64;           // [128][16]  shared input buffer
    float*  P   = (float*)(A + 128 * 16);   // [4][16][PJ] partials

    const int tid   = threadIdx.x;
    const int cta   = blockIdx.x;
    const int hsl   = cta & (HS - 1);
    const int bsl   = cta >> 4;
    const int hbase = hsl * HT;
    const int bbase = bsl * BT;

    // ---- stage weight slices once ----
    for (int i = tid; i < 128 * 64; i += NTHR) {
        int jl = i >> 7;          // /128
        int kp = i & 127;
        int gate = jl >> 4, hh = jl & 15;
        int row = gate * HH + hbase + hh;
        Wp0[(size_t)kp * 64 + jl] = ((const float2*)(W_hh0 + (size_t)row * HH))[kp];
    }
    for (int i = tid; i < 256 * 64; i += NTHR) {
        int jl = i >> 8;          // /256
        int kp = i & 255;
        int gate = jl >> 4, hh = jl & 15;
        int row = gate * HH + hbase + hh;
        float2 w = (kp < 128)
            ? ((const float2*)(W_ih1 + (size_t)row * HH))[kp]
            : ((const float2*)(W_hh1 + (size_t)row * HH))[kp - 128];
        Wp1[(size_t)kp * 64 + jl] = w;
    }

    // ---- GEMM mapping: 8 warps = 4 kgroups x 2 batch halves;
    //      lane = jt*2 + bq -> broadcast-friendly LDS phases ----
    const int wrp = tid >> 5;
    const int kg  = wrp >> 1;            // 0..3
    const int bh  = wrp & 1;
    const int lane = tid & 31;
    const int jt  = lane >> 1;           // 0..15: cols jt*4 .. +3
    const int bq  = lane & 1;
    const int b2  = bh * 8 + bq * 4;     // batches b2 .. b2+3
    const size_t wOff = (size_t)(kg * 32) * 64 + jt * 4;
    const size_t aOff = (size_t)(kg * 32) * 16 + b2;

    // ---- staging maps: 4 uint4 per thread (128 kp x 8 b-pairs) ----
    int    sIdx[4];
    size_t gIdx[4];
    #pragma unroll
    for (int m = 0; m < 4; m++) {
        int e = tid + m * NTHR;          // 0..1023
        int kp = e >> 3;
        int bp = e & 7;
        sIdx[m] = kp * 16 + bp * 2;
        gIdx[m] = (size_t)kp * BB + bbase + bp * 2;
    }

    // ---- epilogue mapping ----
    const int eb = tid >> 4;
    const int eh = tid & 15;
    const float bias1_0 = b_ih1[0 * HH + hbase + eh] + b_hh1[0 * HH + hbase + eh];
    const float bias1_1 = b_ih1[1 * HH + hbase + eh] + b_hh1[1 * HH + hbase + eh];
    const float bias1_2 = b_ih1[2 * HH + hbase + eh] + b_hh1[2 * HH + hbase + eh];
    const float bias1_3 = b_ih1[3 * HH + hbase + eh] + b_hh1[3 * HH + hbase + eh];
    float c0acc = c0[(bbase + eb) * HH + hbase + eh];
    float c1acc = c0[(size_t)BB * HH + (bbase + eb) * HH + hbase + eh];

    const unsigned* flg0_grp = &g_flags[bsl * HS];
    const unsigned* flg1_grp = &g_flags[NCTA + bsl * HS];
    unsigned* flg0_self = &g_flags[cta];
    unsigned* flg1_self = &g_flags[NCTA + cta];

    __syncthreads();   // weights staged

    for (int t = 0; t <= TT; t++) {
        const bool do0 = (t < TT);
        const bool do1 = (t > 0);

        // ---- poll (instant: deps are >= half a slot old) ----
        if (t > 0) {
            if (tid < HS) {                       // y0(t-1) ready?
                const unsigned* fp = flg0_grp + tid;
                unsigned v;
                do { asm volatile("ld.acquire.gpu.global.u32 %0, [%1];" : "=r"(v) : "l"(fp)); }
                while (v < (unsigned)t);
            } else if (tid < 2 * HS) {            // y1(t-2) ready?
                const unsigned* fp = flg1_grp + (tid - HS);
                unsigned v;
                do { asm volatile("ld.acquire.gpu.global.u32 %0, [%1];" : "=r"(v) : "l"(fp)); }
                while (v < (unsigned)(t - 1));
            }
            __syncthreads();   // SYNC0
        }

        // ---- stage A := y0(t-1) (or L0 h-init) ----
        if (t == 0) {
            #pragma unroll
            for (int m = 0; m < 8; m++) {
                int e = tid + m * NTHR;
                int kp = e >> 4, b = e & 15;
                A[kp * 16 + b] = ((const float2*)h0)[(size_t)(bbase + b) * HP + kp];
            }
        } else {
            const float2* src = g_y0 + (size_t)(t - 1) * HP * BB;
            #pragma unroll
            for (int m = 0; m < 4; m++)
                *(uint4*)&A[sIdx[m]] = *(const uint4*)&src[gIdx[m]];
        }
        __syncthreads();   // SYNC1

        // xp0 prefetch for epi0 (consumed after SYNC3 — big slack)
        uint4 xv = make_uint4(0u, 0u, 0u, 0u);
        if (do0)
            xv = *(const uint4*)&g_xp0[(((size_t)t * BB + bbase + eb) * HH
                                        + hbase + eh) * 4];

        uint64_t acc0[4][4] = {};
        uint64_t acc1[4][4] = {};
        if (do0) gemm32(Wp0 + wOff, A + aOff, acc0);        // L0 h-GEMM
        if (do1) gemm32(Wp1 + wOff, A + aOff, acc1);        // L1 x-GEMM
        __syncthreads();   // SYNC2 (A consumed)

        // ---- restage A := y1(t-2) (or L1 h-init); Part := acc0 ----
        if (do1) {
            if (t == 1) {
                const float2* h1i = (const float2*)(h0 + (size_t)BB * HH);
                #pragma unroll
                for (int m = 0; m < 8; m++) {
                    int e = tid + m * NTHR;
                    int kp = e >> 4, b = e & 15;
                    A[kp * 16 + b] = h1i[(size_t)(bbase + b) * HP + kp];
                }
            } else {
                const float2* src = g_y1 + (size_t)(t - 2) * HP * BB;
                #pragma unroll
                for (int m = 0; m < 4; m++)
                    *(uint4*)&A[sIdx[m]] = *(const uint4*)&src[gIdx[m]];
            }
        }
        if (do0) {
            float* pb = P + kg * (16 * PJ) + b2 * PJ + jt * 4;
            #pragma unroll
            for (int bi = 0; bi < 4; bi++) {
                union { uint64_t u; float2 f; } a0, a1, a2, a3;
                a0.u = acc0[0][bi]; a1.u = acc0[1][bi];
                a2.u = acc0[2][bi]; a3.u = acc0[3][bi];
                float4 v;
                v.x = a0.f.x + a0.f.y; v.y = a1.f.x + a1.f.y;
                v.z = a2.f.x + a2.f.y; v.w = a3.f.x + a3.f.y;
                *(float4*)(pb + bi * PJ) = v;
            }
        }
        __syncthreads();   // SYNC3

        if (do1) gemm32(Wp1 + (size_t)128 * 64 + wOff, A + aOff, acc1);  // L1 h-GEMM

        // ---- epi0 (reads P + xp0) ----
        if (do0) {
            float4 xf = *(float4*)&xv;
            float s0 = xf.x, s1 = xf.y, s2 = xf.z, s3 = xf.w;
            #pragma unroll
            for (int p = 0; p < 4; p++) {
                const float* pp = P + p * (16 * PJ) + eb * PJ;
                s0 += pp[ 0 + eh];
                s1 += pp[16 + eh];
                s2 += pp[32 + eh];
                s3 += pp[48 + eh];
            }
            const float ig = fast_sigmoid(s0);
            const float fg = fast_sigmoid(s1);
            const float gt = fast_tanh(s2);
            const float og = fast_sigmoid(s3);
            c0acc = fg * c0acc + ig * gt;
            const float hv = og * fast_tanh(c0acc);
            const float hv1 = __shfl_down_sync(0xffffffffu, hv, 1);
            if (!(eh & 1))
                g_y0[(size_t)t * HP * BB + ((hbase + eh) >> 1) * BB + (bbase + eb)] =
                    make_float2(hv, hv1);
            if (t == TT - 1) {
                hn[(bbase + eb) * HH + hbase + eh] = hv;
                cn[(bbase + eb) * HH + hbase + eh] = c0acc;
            }
        }
        __syncthreads();   // SYNC4 (y0 stores + P reads done)
        if (do0 && tid == 0)
            asm volatile("st.release.gpu.global.u32 [%0], %1;"
                         :: "l"(flg0_self), "r"((unsigned)(t + 1)) : "memory");

        // ---- Part := acc1; epi1 ----
        if (do1) {
            float* pb = P + kg * (16 * PJ) + b2 * PJ + jt * 4;
            #pragma unroll
            for (int bi = 0; bi < 4; bi++) {
                union { uint64_t u; float2 f; } a0, a1, a2, a3;
                a0.u = acc1[0][bi]; a1.u = acc1[1][bi];
                a2.u = acc1[2][bi]; a3.u = acc1[3][bi];
                float4 v;
                v.x = a0.f.x + a0.f.y; v.y = a1.f.x + a1.f.y;
                v.z = a2.f.x + a2.f.y; v.w = a3.f.x + a3.f.y;
                *(float4*)(pb + bi * PJ) = v;
            }
        }
        __syncthreads();   // SYNC5
        if (do1) {
            float s0 = bias1_0, s1 = bias1_1, s2 = bias1_2, s3 = bias1_3;
            #pragma unroll
            for (int p = 0; p < 4; p++) {
                const float* pp = P + p * (16 * PJ) + eb * PJ;
                s0 += pp[ 0 + eh];
                s1 += pp[16 + eh];
                s2 += pp[32 + eh];
                s3 += pp[48 + eh];
            }
            const float ig = fast_sigmoid(s0);
            const float fg = fast_sigmoid(s1);
            const float gt = fast_tanh(s2);
            const float og = fast_sigmoid(s3);
            c1acc = fg * c1acc + ig * gt;
            const float hv = og * fast_tanh(c1acc);
            const float hv1 = __shfl_down_sync(0xffffffffu, hv, 1);
            if (!(eh & 1))
                g_y1[(size_t)(t - 1) * HP * BB + ((hbase + eh) >> 1) * BB + (bbase + eb)] =
                    make_float2(hv, hv1);
            if (t - 1 == TT - 1) {
                hn[(size_t)BB * HH + (bbase + eb) * HH + hbase + eh] = hv;
                cn[(size_t)BB * HH + (bbase + eb) * HH + hbase + eh] = c1acc;
            }
        }
        __syncthreads();   // SYNC6 (y1 stores + P reads done)
        if (do1 && tid == 0)
            asm volatile("st.release.gpu.global.u32 [%0], %1;"
                         :: "l"(flg1_self), "r"((unsigned)t) : "memory");
    }
}

// Final projection + softplus: out[t][b][o] = softplus(y1[t]·W_out^T + b_out)
__global__ void __launch_bounds__(128, 4)
proj_kernel(const float* __restrict__ W_out,  // (33, 256)
            const float* __restrict__ b_out,  // (33,)
            float* __restrict__ out)          // [T][B][33]
{
    __shared__ float Wsm[HH * OO];   // [k][o]
    const int t = blockIdx.x;
    const int b = threadIdx.x;       // 0..127

    for (int i = b; i < HH * OO; i += 128) {
        int k = i / OO;
        int o = i - k * OO;
        Wsm[k * OO + o] = W_out[o * HH + k];
    }
    __syncthreads();

    const float2* y = g_y1 + (size_t)t * HP * BB;   // [hpair][B]
    float acc[OO];
    #pragma unroll
    for (int o = 0; o < OO; o++) acc[o] = b_out[o];

    #pragma unroll 2
    for (int kp = 0; kp < HP; kp++) {
        const float2 v = y[kp * BB + b];
        const float* w0 = &Wsm[(2 * kp) * OO];
        const float* w1 = &Wsm[(2 * kp + 1) * OO];
        #pragma unroll
        for (int o = 0; o < OO; o++) acc[o] += v.x * w0[o] + v.y * w1[o];
    }

    float* op = out + (size_t)t * BB * OO + b * OO;
    #pragma unroll
    for (int o = 0; o < OO; o++) {
        const float x = acc[o];
        op[o] = fmaxf(x, 0.f) + log1pf(__expf(-fabsf(x)));
    }
}

extern "C" void kernel_launch(void* const* d_in, const int* in_sizes, int n_in,
                              void* d_out, int out_size) {
    const float* x     = (const float*)d_in[0];
    const float* h0    = (const float*)d_in[1];   // (2,B,H)
    const float* c0    = (const float*)d_in[2];   // (2,B,H)
    const float* W_ih0 = (const float*)d_in[3];
    const float* W_hh0 = (const float*)d_in[4];
    const float* b_ih0 = (const float*)d_in[5];
    const float* b_hh0 = (const float*)d_in[6];
    const float* W_ih1 = (const float*)d_in[7];
    const float* W_hh1 = (const float*)d_in[8];
    const float* b_ih1 = (const float*)d_in[9];
    const float* b_hh1 = (const float*)d_in[10];
    const float* W_out = (const float*)d_in[11];
    const float* b_out = (const float*)d_in[12];

    float* out = (float*)d_out;
    float* hn  = out + (size_t)TT * BB * OO;   // (2,B,H)
    float* cn  = hn + 2 * BB * HH;             // (2,B,H)

    // smem: Wp0 64K + Wp1 128K + A 16K + P 4*16*68*4 = 230,400 B
    const int smemF = 128 * 64 * 8 + 256 * 64 * 8 + 128 * 16 * 8 + 4 * 16 * PJ * 4;
    cudaFuncSetAttribute((const void*)lstm_fused_kernel,
                         cudaFuncAttributeMaxDynamicSharedMemorySize, smemF);

    reset_kernel<<<1, 256>>>();

    dim3 xg(TT, 8, 2);
    xp0_kernel<<<xg, 256>>>(x, W_ih0, b_ih0, b_hh0);

    lstm_fused_kernel<<<NCTA, NTHR, smemF>>>(
        W_hh0, W_ih1, W_hh1, b_ih1, b_hh1, h0, c0, hn, cn);

    proj_kernel<<<TT, 128>>>(W_out, b_out, out);
}